// round 2
// baseline (speedup 1.0000x reference)
#include <cuda_runtime.h>

// ---------------------------------------------------------------------------
// CorrelationPyramid: proj(1x1 conv C=128->64) -> pyramid avg-pool ->
// L2-normalized banded circular correlation at 4 levels.
// Layout of scratch features: channel-planar [img][c][h][w], img = 0..1 (q b),
// 2..9 (v b*4+n). Normalization folded into epilogue via inverse norms.
// ---------------------------------------------------------------------------

#define HW0 25600   // 160*160

__device__ float g_F0[10 * 64 * 25600];
__device__ float g_F1[10 * 64 * 6400];
__device__ float g_F2[10 * 64 * 1600];
__device__ float g_F3[10 * 64 * 400];
__device__ float g_I0[10 * 25600];
__device__ float g_I1[10 * 6400];
__device__ float g_I2[10 * 1600];
__device__ float g_I3[10 * 400];

// ---------------------------------------------------------------------------
// Projection: per image (10 images of [128, 25600]), Y[p][o] = sum_c W[o][c] X[c][p] + b[o]
// Output stored channel-planar: dst[o * HW0 + p].
// Block: 256 threads = 8 warps (warp = 8-output group) x 32 lanes (lane = 4 pixels).
// Tile: 128 pixels x 64 outputs x full K=128 (staged 16 channels at a time).
// ---------------------------------------------------------------------------
__global__ __launch_bounds__(256) void proj_kernel(
    const float* __restrict__ qf, const float* __restrict__ vf,
    const float* __restrict__ pw, const float* __restrict__ pb) {
  __shared__ float Wsh[8192];   // Wsh[c*64 + o] = pw[o*128 + c]
  __shared__ float Bsh[64];
  __shared__ float Xs[16][128];

  const int img = blockIdx.y;
  const float* src = (img < 2) ? qf + (size_t)img * 128 * HW0
                               : vf + (size_t)(img - 2) * 128 * HW0;
  float* dst = g_F0 + (size_t)img * 64 * HW0;

  const int t = threadIdx.x;
  // Load W transposed into smem (linear smem index -> conflict-free stores).
  for (int i = t; i < 8192; i += 256) Wsh[i] = pw[(i & 63) * 128 + (i >> 6)];
  if (t < 64) Bsh[t] = pb[t];

  const int og = t >> 5;           // output group 0..7 (8 outputs each)
  const int lane = t & 31;
  const int pxb = blockIdx.x * 128;
  const int px = lane * 4;

  float acc[8][4];
#pragma unroll
  for (int o = 0; o < 8; o++)
#pragma unroll
    for (int i = 0; i < 4; i++) acc[o][i] = 0.f;

  for (int ch = 0; ch < 8; ch++) {
    __syncthreads();
#pragma unroll
    for (int j = 0; j < 2; j++) {
      int idx = t * 2 + j;               // 0..511 float4 slots
      int r = idx >> 5, c4 = (idx & 31) * 4;
      float4 v = *reinterpret_cast<const float4*>(
          src + (size_t)(ch * 16 + r) * HW0 + pxb + c4);
      *reinterpret_cast<float4*>(&Xs[r][c4]) = v;
    }
    __syncthreads();
#pragma unroll
    for (int c = 0; c < 16; c++) {
      float4 x = *reinterpret_cast<const float4*>(&Xs[c][px]);
      const float* wrow = &Wsh[(ch * 16 + c) * 64 + og * 8];
      float4 wa = *reinterpret_cast<const float4*>(wrow);
      float4 wb = *reinterpret_cast<const float4*>(wrow + 4);
      float w[8] = {wa.x, wa.y, wa.z, wa.w, wb.x, wb.y, wb.z, wb.w};
#pragma unroll
      for (int o = 0; o < 8; o++) {
        acc[o][0] += w[o] * x.x;
        acc[o][1] += w[o] * x.y;
        acc[o][2] += w[o] * x.z;
        acc[o][3] += w[o] * x.w;
      }
    }
  }

#pragma unroll
  for (int o = 0; o < 8; o++) {
    float b = Bsh[og * 8 + o];
    float4 r;
    r.x = acc[o][0] + b; r.y = acc[o][1] + b;
    r.z = acc[o][2] + b; r.w = acc[o][3] + b;
    *reinterpret_cast<float4*>(dst + (size_t)(og * 8 + o) * HW0 + pxb + px) = r;
  }
}

// ---------------------------------------------------------------------------
// 2x2 avg pool over channel-planar features. One thread -> 2 output floats.
// ---------------------------------------------------------------------------
__global__ __launch_bounds__(256) void pool_kernel(
    const float* __restrict__ in, float* __restrict__ out,
    int Hin, int Win, int total2) {
  int idx = blockIdx.x * 256 + threadIdx.x;
  if (idx >= total2) return;
  int Wo = Win >> 1, Ho = Hin >> 1;
  int w2 = Wo >> 1;
  int x2 = idx % w2;
  int rest = idx / w2;
  int y = rest % Ho;
  int plane = rest / Ho;   // 0..639 (10 imgs * 64 ch)
  const float* p = in + (size_t)plane * Hin * Win + (size_t)(2 * y) * Win + 4 * x2;
  float4 a = *reinterpret_cast<const float4*>(p);
  float4 b = *reinterpret_cast<const float4*>(p + Win);
  float2 o;
  o.x = 0.25f * (a.x + a.y + b.x + b.y);
  o.y = 0.25f * (a.z + a.w + b.z + b.w);
  *reinterpret_cast<float2*>(out + (size_t)plane * Ho * Wo + (size_t)y * Wo + 2 * x2) = o;
}

// ---------------------------------------------------------------------------
// Per-pixel inverse L2 norm over 64 channels (channel-planar reads, coalesced).
// ---------------------------------------------------------------------------
__global__ __launch_bounds__(256) void invnorm_kernel(
    const float* __restrict__ F, float* __restrict__ I, int HW, int total) {
  int idx = blockIdx.x * 256 + threadIdx.x;
  if (idx >= total) return;
  int img = idx / HW;
  int p = idx - img * HW;
  const float* f = F + (size_t)img * 64 * HW + p;
  float s = 0.f;
#pragma unroll
  for (int c = 0; c < 64; c++) {
    float v = f[(size_t)c * HW];
    s += v * v;
  }
  I[idx] = 1.f / fmaxf(sqrtf(s), 1e-12f);
}

// ---------------------------------------------------------------------------
// Banded circular correlation, radius R.
// corr[bn,h,w,(dy+R)*(2R+1)+(dx+R)] = q[h,w] . v[(h-dy)%H,(w-dx)%W] * invq * invv
// Block: (2R+1) warps; warp <-> dy. Tile: 4 rows x 32 cols of query pixels.
// Lane: prow = lane/8 (query row in tile), 4 consecutive-w pixels.
// Channel staged in chunks of 16 through smem; sliding-window v reuse in regs.
// ---------------------------------------------------------------------------
template <int R>
__global__ void corr_kernel(const float* __restrict__ F, const float* __restrict__ I,
                            float* __restrict__ out, int H, int W) {
  constexpr int NW = 2 * R + 1;
  constexpr int VH = 4 + 2 * R;
  constexpr int VW = ((32 + 2 * R + 3) & ~3);   // padded halo width (mult of 4)
  constexpr int NV4 = (4 + 2 * R + 3) / 4;      // float4 loads per v window
  constexpr int NT = NW * 32;

  __shared__ float qs[16][128];
  __shared__ float vs[16][VH][VW];
  __shared__ float ivs[VH][VW];
  __shared__ float iqs[128];

  const int bn = blockIdx.z;          // 0..7 = b*4+n
  const int b = bn >> 2;
  const int HWl = H * W;
  const float* Fq = F + (size_t)b * 64 * HWl;
  const float* Fv = F + (size_t)(2 + bn) * 64 * HWl;
  const float* Iq = I + (size_t)b * HWl;
  const float* Iv = I + (size_t)(2 + bn) * HWl;

  const int tx = blockIdx.x * 32, ty = blockIdx.y * 4;
  const int t = threadIdx.x, lane = t & 31, warp = t >> 5;
  const int dy = warp - R;
  const int prow = lane >> 3;
  const int pc = (lane & 7) * 4;

  // inverse-norm tiles
  for (int i = t; i < 128; i += NT) {
    int w = tx + (i & 31);
    iqs[i] = (w < W) ? Iq[(ty + (i >> 5)) * W + w] : 0.f;
  }
  for (int i = t; i < VH * VW; i += NT) {
    int r = i / VW, c = i - r * VW;
    int h = ty + r - R; if (h < 0) h += H; if (h >= H) h -= H;
    int w = tx + c - R; if (w < 0) w += W; if (w >= W) w -= W;
    ivs[r][c] = Iv[h * W + w];
  }

  float acc[4][NW];
#pragma unroll
  for (int i = 0; i < 4; i++)
#pragma unroll
    for (int k = 0; k < NW; k++) acc[i][k] = 0.f;

  const int vr = prow + R - dy;   // v smem row for this warp's dy

  for (int ch = 0; ch < 4; ch++) {
    __syncthreads();
    // stage q chunk: 16 ch x (4 rows x 32 cols)
    for (int i = t; i < 2048; i += NT) {
      int c = i >> 7, rem = i & 127;
      int w = tx + (rem & 31);
      qs[c][rem] = (w < W)
          ? Fq[(size_t)(ch * 16 + c) * HWl + (ty + (rem >> 5)) * W + w]
          : 0.f;
    }
    // stage v halo chunk: 16 ch x VH x VW, circular wrap
    for (int i = t; i < 16 * VH * VW; i += NT) {
      int c = i / (VH * VW), rem = i - c * (VH * VW);
      int r = rem / VW, col = rem - r * VW;
      int h = ty + r - R; if (h < 0) h += H; if (h >= H) h -= H;
      int w = tx + col - R; if (w < 0) w += W; if (w >= W) w -= W;
      vs[c][r][col] = Fv[(size_t)(ch * 16 + c) * HWl + h * W + w];
    }
    __syncthreads();

#pragma unroll
    for (int c = 0; c < 16; c++) {
      float4 q = *reinterpret_cast<const float4*>(&qs[c][(prow << 5) + pc]);
      float qa[4] = {q.x, q.y, q.z, q.w};
      float vwin[NV4 * 4];
#pragma unroll
      for (int j = 0; j < NV4; j++)
        *reinterpret_cast<float4*>(&vwin[j * 4]) =
            *reinterpret_cast<const float4*>(&vs[c][vr][pc + j * 4]);
#pragma unroll
      for (int k = 0; k < NW; k++) {   // k = dx + R
#pragma unroll
        for (int i = 0; i < 4; i++)
          acc[i][k] += qa[i] * vwin[i + 2 * R - k];
      }
    }
  }

  // epilogue: scale by inverse norms, write banded output
  const int h = ty + prow;
#pragma unroll
  for (int i = 0; i < 4; i++) {
    const int w = tx + pc + i;
    if (w >= W) continue;
    const float qi = iqs[(prow << 5) + pc + i];
    float* op = out + ((size_t)(bn * H + h) * W + w) * (NW * NW) + (dy + R) * NW;
#pragma unroll
    for (int k = 0; k < NW; k++) {
      op[k] = acc[i][k] * qi * ivs[vr][pc + i + 2 * R - k];
    }
  }
}

// ---------------------------------------------------------------------------

extern "C" void kernel_launch(void* const* d_in, const int* in_sizes, int n_in,
                              void* d_out, int out_size) {
  const float* qf = (const float*)d_in[0];   // [2,128,160,160]
  const float* vf = (const float*)d_in[1];   // [2,4,128,160,160]
  const float* pw = (const float*)d_in[2];   // [64,128]
  const float* pb = (const float*)d_in[3];   // [64]
  float* out = (float*)d_out;

  float *F0, *F1, *F2, *F3, *I0, *I1, *I2, *I3;
  cudaGetSymbolAddress((void**)&F0, g_F0);
  cudaGetSymbolAddress((void**)&F1, g_F1);
  cudaGetSymbolAddress((void**)&F2, g_F2);
  cudaGetSymbolAddress((void**)&F3, g_F3);
  cudaGetSymbolAddress((void**)&I0, g_I0);
  cudaGetSymbolAddress((void**)&I1, g_I1);
  cudaGetSymbolAddress((void**)&I2, g_I2);
  cudaGetSymbolAddress((void**)&I3, g_I3);

  // 1) projection -> level-0 features (channel-planar)
  proj_kernel<<<dim3(HW0 / 128, 10), 256>>>(qf, vf, pw, pb);

  // 2) pooling pyramid
  {
    int t1 = 640 * 80 * 40;   // 10*64 planes, Ho=80, Wo/2=40
    pool_kernel<<<(t1 + 255) / 256, 256>>>(F0, F1, 160, 160, t1);
    int t2 = 640 * 40 * 20;
    pool_kernel<<<(t2 + 255) / 256, 256>>>(F1, F2, 80, 80, t2);
    int t3 = 640 * 20 * 10;
    pool_kernel<<<(t3 + 255) / 256, 256>>>(F2, F3, 40, 40, t3);
  }

  // 3) inverse norms per level
  {
    int n0 = 10 * 25600, n1 = 10 * 6400, n2 = 10 * 1600, n3 = 10 * 400;
    invnorm_kernel<<<(n0 + 255) / 256, 256>>>(F0, I0, 25600, n0);
    invnorm_kernel<<<(n1 + 255) / 256, 256>>>(F1, I1, 6400, n1);
    invnorm_kernel<<<(n2 + 255) / 256, 256>>>(F2, I2, 1600, n2);
    invnorm_kernel<<<(n3 + 255) / 256, 256>>>(F3, I3, 400, n3);
  }

  // 4) correlations (output = concat of the 4 level tensors)
  size_t o0 = 0;
  size_t o1 = o0 + (size_t)8 * 25600 * 81;   // 16,588,800
  size_t o2 = o1 + (size_t)8 * 6400 * 25;    // +1,280,000
  size_t o3 = o2 + (size_t)8 * 1600 * 9;     // +115,200
  corr_kernel<4><<<dim3(5, 40, 8), 288>>>(F0, I0, out + o0, 160, 160);
  corr_kernel<2><<<dim3(3, 20, 8), 160>>>(F1, I1, out + o1, 80, 80);
  corr_kernel<1><<<dim3(2, 10, 8), 96>>>(F2, I2, out + o2, 40, 40);
  corr_kernel<1><<<dim3(1, 5, 8), 96>>>(F3, I3, out + o3, 20, 20);
}